// round 14
// baseline (speedup 1.0000x reference)
#include <cuda_runtime.h>
#include <cuda_bf16.h>
#include <cstdint>

constexpr int B    = 32;
constexpr int H    = 1024;
constexpr int MEL  = 128;
constexpr int TENC = 512;
constexpr int TMEL = 400;
constexpr int H4   = H / 4;

constexpr size_t OFF_GATE = (size_t)B * TMEL * MEL;
constexpr size_t OFF_MASK = OFF_GATE + (size_t)B * TMEL;

// ---------------- device scratch (no allocations allowed) -------------------
__device__ float g_WT[(size_t)H * H];       // W_attn^T
__device__ float g_h0[2][B * H];
__device__ float g_h1[2][B * H];
__device__ float g_decin[B * MEL];
__device__ float g_v[B * H];
__device__ float g_co[B * H];
// attention partials: 4 t-tiles of 128
__device__ float pm[4][B];
__device__ float pl[4][B];
__device__ float pctx[4][B * H];

// barriers
__device__ unsigned g_bar_arrive = 0;
__device__ volatile unsigned g_bar_gen = 0;
__device__ volatile unsigned g_arr[152 * 8];
__device__ volatile unsigned g_release;

// ---------------- helpers ----------------------------------------------------
__device__ __forceinline__ float wsum(float v) {
    v += __shfl_xor_sync(0xffffffffu, v, 16);
    v += __shfl_xor_sync(0xffffffffu, v, 8);
    v += __shfl_xor_sync(0xffffffffu, v, 4);
    v += __shfl_xor_sync(0xffffffffu, v, 2);
    v += __shfl_xor_sync(0xffffffffu, v, 1);
    return v;
}
__device__ __forceinline__ float dot4(float4 a, float4 b, float acc) {
    acc = fmaf(a.x, b.x, acc);
    acc = fmaf(a.y, b.y, acc);
    acc = fmaf(a.z, b.z, acc);
    acc = fmaf(a.w, b.w, acc);
    return acc;
}
__device__ __forceinline__ float sigmoidf_(float x) { return 1.f / (1.f + expf(-x)); }

__device__ __forceinline__ void abar(int nblk) {
    __syncthreads();
    if (threadIdx.x == 0) {
        __threadfence();
        unsigned gen = g_bar_gen;
        if (atomicAdd(&g_bar_arrive, 1u) == (unsigned)nblk - 1u) {
            g_bar_arrive = 0;
            __threadfence();
            g_bar_gen = gen + 1u;
        } else {
            while (g_bar_gen == gen) { __nanosleep(64); }
        }
        __threadfence();
    }
    __syncthreads();
}

// grid barrier: per-block arrive slots, block 0 scans, others poll one word.
__device__ __forceinline__ void sbar(int nblk, int bx, unsigned gen) {
    __syncthreads();
    if (threadIdx.x == 0) { __threadfence(); g_arr[bx * 8] = gen; }
    if (bx == 0) {
        if (threadIdx.x < 32) {
            for (;;) {
                bool ok = true;
                for (int i = threadIdx.x; i < nblk; i += 32)
                    ok &= (g_arr[i * 8] >= gen);
                if (__all_sync(0xffffffffu, ok)) break;
                __nanosleep(32);
            }
            if (threadIdx.x == 0) { __threadfence(); g_release = gen; }
        }
    } else if (threadIdx.x == 0) {
        while (g_release < gen) { __nanosleep(64); }
        __threadfence();
    }
    __syncthreads();
}

__device__ __forceinline__ void stage(float4* dst, const float* src, int n4, int tid) {
    const float4* s = reinterpret_cast<const float4*>(src);
    for (int i = tid; i < n4; i += 512) dst[i] = s[i];
}

// 3-row dot vs 8 batches (acts in smem), weight prefetch depth 2.
__device__ __forceinline__ void dot3(
    const float4* __restrict__ w0, const float4* __restrict__ w1,
    const float4* __restrict__ w2,
    const float4* __restrict__ actb, int bstride4, int nIt, int lane,
    float A0[8], float A1[8], float A2[8])
{
    float4 c0 = w0[lane], c1 = w1[lane], c2 = w2[lane];
    float4 n0 = c0, n1 = c1, n2 = c2;
    if (nIt > 1) { n0 = w0[lane + 32]; n1 = w1[lane + 32]; n2 = w2[lane + 32]; }
    for (int i = 0; i < nIt; ++i) {
        float4 p0 = n0, p1 = n1, p2 = n2;
        if (i + 2 < nIt) {
            p0 = w0[lane + (i + 2) * 32];
            p1 = w1[lane + (i + 2) * 32];
            p2 = w2[lane + (i + 2) * 32];
        }
        const float4* a = actb + i * 32 + lane;
#pragma unroll
        for (int bb = 0; bb < 8; ++bb) {
            float4 av = a[bb * bstride4];
            A0[bb] = dot4(c0, av, A0[bb]);
            A1[bb] = dot4(c1, av, A1[bb]);
            A2[bb] = dot4(c2, av, A2[bb]);
        }
        c0 = n0; c1 = n1; c2 = n2;
        n0 = p0; n1 = p1; n2 = p2;
    }
}

// 1-row dot vs 8 batches, prefetch depth 2.
__device__ __forceinline__ void dot1(
    const float4* __restrict__ w,
    const float4* __restrict__ actb, int bstride4, int nIt, int lane,
    float A[8])
{
    float4 c = w[lane];
    float4 n = c;
    if (nIt > 1) n = w[lane + 32];
    for (int i = 0; i < nIt; ++i) {
        float4 p = n;
        if (i + 2 < nIt) p = w[lane + (i + 2) * 32];
        const float4* a = actb + i * 32 + lane;
#pragma unroll
        for (int bb = 0; bb < 8; ++bb)
            A[bb] = dot4(c, a[bb * bstride4], A[bb]);
        c = n; n = p;
    }
}

// merged GRU cell: acts from smem, direct state write
__device__ __forceinline__ void gru_sm(
    int j, int bl0, int lane, int hb0,
    const float4* __restrict__ smX, int XD,
    const float4* __restrict__ smH, const float* __restrict__ smHf,
    float* __restrict__ hnew,
    const float* __restrict__ Wih, const float* __restrict__ Whh,
    const float* __restrict__ bih, const float* __restrict__ bhh)
{
    const int XD4 = XD >> 2, nItX = XD4 >> 5;
    float ar[8], az[8], ani[8], anh[8];
#pragma unroll
    for (int i = 0; i < 8; ++i) { ar[i] = 0.f; az[i] = 0.f; ani[i] = 0.f; anh[i] = 0.f; }

    dot3(reinterpret_cast<const float4*>(Wih + (size_t)j * XD),
         reinterpret_cast<const float4*>(Wih + (size_t)(H + j) * XD),
         reinterpret_cast<const float4*>(Wih + (size_t)(2 * H + j) * XD),
         smX + bl0 * XD4, XD4, nItX, lane, ar, az, ani);
    dot3(reinterpret_cast<const float4*>(Whh + (size_t)j * H),
         reinterpret_cast<const float4*>(Whh + (size_t)(H + j) * H),
         reinterpret_cast<const float4*>(Whh + (size_t)(2 * H + j) * H),
         smH + bl0 * H4, H4, 8, lane, ar, az, anh);

    const float br  = bih[j] + bhh[j];
    const float bz  = bih[H + j] + bhh[H + j];
    const float bni = bih[2 * H + j];
    const float bnh = bhh[2 * H + j];
#pragma unroll
    for (int bb = 0; bb < 8; ++bb) {
        float r  = wsum(ar[bb]);
        float z  = wsum(az[bb]);
        float ni = wsum(ani[bb]);
        float nh = wsum(anh[bb]);
        if (lane == bb) {
            float rr = sigmoidf_(r + br);
            float zz = sigmoidf_(z + bz);
            float hp = smHf[(bl0 + bb) * H + j];
            float nn = tanhf(ni + bni + rr * (nh + bnh));
            hnew[(hb0 + bl0 + bb) * H + j] = (1.f - zz) * nn + zz * hp;
        }
    }
}

// ---------------- main persistent kernel -------------------------------------
__global__ void __launch_bounds__(512, 1)
decoder_kernel(const float* __restrict__ enc_hidden,
               const float* __restrict__ enc_out,
               const int*   __restrict__ lens,
               const float* __restrict__ W_attn, const float* __restrict__ b_attn,
               const float* __restrict__ Wih0, const float* __restrict__ Whh0,
               const float* __restrict__ bih0, const float* __restrict__ bhh0,
               const float* __restrict__ Wih1, const float* __restrict__ Whh1,
               const float* __restrict__ bih1, const float* __restrict__ bhh1,
               const float* __restrict__ Wc,   const float* __restrict__ bc,
               const float* __restrict__ Wp,   const float* __restrict__ bp,
               const float* __restrict__ Wg,   const float* __restrict__ bg,
               float* __restrict__ out, int nblk) {
    extern __shared__ float4 sm4[];
    float4* smA = sm4;                 // 64 KB
    float4* smB = sm4 + 4096;          // 64 KB
    const float* smBf = reinterpret_cast<const float*>(smB);
    float* smV = reinterpret_cast<float*>(sm4);   // ATT: v[b] (4 KB)

    __shared__ float smS[16];          // subtile scores
    __shared__ float smP[16];          // subtile exp weights
    __shared__ float smW[64];          // per-batch combine weights (4 tiles x 16)

    const int tid  = threadIdx.x;
    const int lane = tid & 31;
    const int wid  = tid >> 5;
    const int bx   = blockIdx.x;
    const int half = bx & 1;
    const int bq   = bx >> 1;
    const int nbh  = nblk >> 1;
    const int wq   = bq * 16 + wid;
    const int NWQ  = nbh * 16;
    const int hb0  = half * 16;
    const int gtid = bx * blockDim.x + tid;
    const int gsz  = nblk * blockDim.x;

    // ================= init =================
    for (int i = gtid; i < H * H; i += gsz) {
        int c = i >> 10, j = i & (H - 1);
        g_WT[i] = W_attn[(size_t)j * H + c];
    }
    for (int i = gtid; i < B * H; i += gsz) {
        g_h0[0][i] = enc_hidden[i];
        g_h1[0][i] = enc_hidden[B * H + i];
    }
    for (int i = gtid; i < B * MEL; i += gsz) g_decin[i] = 0.f;
    for (int i = gtid; i < B * TMEL; i += gsz) {
        int b = i / TMEL, t = i - b * TMEL;
        out[OFF_MASK + i] = (t > lens[b]) ? 1.f : 0.f;
    }
    for (int i = gtid; i < 152 * 8; i += gsz) g_arr[i] = 0u;
    if (gtid == 0) g_release = 0u;
    abar(nblk);

    unsigned gen = 0;

    // ================= 400 autoregressive steps =================
    for (int step = 0; step < TMEL; ++step) {
        const int cur = step & 1, nxt = cur ^ 1;

        // ---- GRU layer 0 ----
        stage(smA, g_decin + hb0 * MEL, 16 * MEL / 4, tid);
        stage(smB, g_h0[cur] + hb0 * H, 4096, tid);
        __syncthreads();
        for (int job = wq; job < 2048; job += NWQ)
            gru_sm(job >> 1, (job & 1) * 8, lane, hb0, smA, MEL, smB, smBf,
                   g_h0[nxt], Wih0, Whh0, bih0, bhh0);
        sbar(nblk, bx, ++gen);

        // ---- GRU layer 1 ----
        stage(smA, g_h0[nxt] + hb0 * H, 4096, tid);
        stage(smB, g_h1[cur] + hb0 * H, 4096, tid);
        __syncthreads();
        for (int job = wq; job < 2048; job += NWQ)
            gru_sm(job >> 1, (job & 1) * 8, lane, hb0, smA, H, smB, smBf,
                   g_h1[nxt], Wih1, Whh1, bih1, bhh1);
        sbar(nblk, bx, ++gen);

        // ---- Pv: v = W_attn^T h1 (bias drops in softmax) ----
        stage(smA, g_h1[nxt] + hb0 * H, 4096, tid);
        __syncthreads();
        for (int job = wq; job < 2048; job += NWQ) {
            const int c   = job >> 1;
            const int bl0 = (job & 1) * 8;
            float acc[8];
#pragma unroll
            for (int i = 0; i < 8; ++i) acc[i] = 0.f;
            dot1(reinterpret_cast<const float4*>(g_WT + (size_t)c * H),
                 smA + bl0 * H4, H4, 8, lane, acc);
#pragma unroll
            for (int bb = 0; bb < 8; ++bb) {
                float s = wsum(acc[bb]);
                if (lane == bb) g_v[(hb0 + bl0 + bb) * H + c] = s;
            }
        }
        sbar(nblk, bx, ++gen);

        // ---- ATT: fused scores+softmax+context, enc read ONCE (L2-cached) ----
        for (int job = bx; job < 128; job += nblk) {
            const int b    = job >> 2;
            const int tile = job & 3;
            const int t0   = tile * 128;
            __syncthreads();
            for (int i = tid; i < 1024; i += 512) smV[i] = g_v[b * H + i];
            __syncthreads();

            float m_run = -1e30f, l_run = 0.f;
            float a0 = 0.f, a1 = 0.f;
            const int hc = wid * 64;

            for (int sub = 0; sub < 8; ++sub) {
                const int ts = t0 + sub * 16;
                // scores: warp wid computes t = ts + wid
                {
                    const float4* er = reinterpret_cast<const float4*>(
                        enc_out + ((size_t)b * TENC + ts + wid) * H);
                    const float4* v4 = reinterpret_cast<const float4*>(smV);
                    float acc = 0.f;
#pragma unroll
                    for (int k = 0; k < 8; ++k) {
                        float4 ev = er[k * 32 + lane];
                        acc = dot4(v4[k * 32 + lane], ev, acc);
                    }
                    acc = wsum(acc);
                    if (lane == 0) smS[wid] = acc;
                }
                __syncthreads();
                float msub = -1e30f;
#pragma unroll
                for (int i = 0; i < 16; ++i) msub = fmaxf(msub, smS[i]);
                const float m_new = fmaxf(m_run, msub);
                if (lane == 0) smP[wid] = expf(smS[wid] - m_new);
                const float scale = expf(m_run - m_new);
                __syncthreads();
                // context accumulate for this warp's 64-wide h-chunk
                a0 *= scale; a1 *= scale;
                float lsub = 0.f;
                const float* eb = enc_out + ((size_t)b * TENC + ts) * H + hc + lane;
#pragma unroll 4
                for (int t = 0; t < 16; ++t) {
                    float p = smP[t];
                    lsub += p;
                    a0 = fmaf(p, eb[(size_t)t * H], a0);
                    a1 = fmaf(p, eb[(size_t)t * H + 32], a1);
                }
                l_run = l_run * scale + lsub;
                m_run = m_new;
                __syncthreads();
            }
            // write tile partials (unnormalized)
            pctx[tile][b * H + hc + lane]      = a0;
            pctx[tile][b * H + hc + 32 + lane] = a1;
            if (tid == 0) { pm[tile][b] = m_run; pl[tile][b] = l_run; }
        }
        sbar(nblk, bx, ++gen);

        const float* h1n = g_h1[nxt];

        // ---- P5: combine ctx tiles into smB, stage h1 into smA, then GEMM ----
        if (tid < 16) {
            const int b = hb0 + tid;
            float m0 = pm[0][b], m1 = pm[1][b], m2 = pm[2][b], m3 = pm[3][b];
            float M = fmaxf(fmaxf(m0, m1), fmaxf(m2, m3));
            float e0 = expf(m0 - M), e1 = expf(m1 - M);
            float e2 = expf(m2 - M), e3 = expf(m3 - M);
            float invL = 1.f / (e0 * pl[0][b] + e1 * pl[1][b] +
                                e2 * pl[2][b] + e3 * pl[3][b]);
            smW[tid]      = e0 * invL;
            smW[16 + tid] = e1 * invL;
            smW[32 + tid] = e2 * invL;
            smW[48 + tid] = e3 * invL;
        }
        stage(smA, h1n + hb0 * H, 4096, tid);
        __syncthreads();
        for (int i = tid; i < 4096; i += 512) {
            const int bl = i >> 8;
            const size_t off = (size_t)(hb0 + bl) * 256 + (i & 255);
            float w0 = smW[bl], w1 = smW[16 + bl], w2 = smW[32 + bl], w3 = smW[48 + bl];
            float4 c0 = reinterpret_cast<const float4*>(pctx[0])[off];
            float4 c1 = reinterpret_cast<const float4*>(pctx[1])[off];
            float4 c2 = reinterpret_cast<const float4*>(pctx[2])[off];
            float4 c3 = reinterpret_cast<const float4*>(pctx[3])[off];
            float4 r;
            r.x = w0 * c0.x + w1 * c1.x + w2 * c2.x + w3 * c3.x;
            r.y = w0 * c0.y + w1 * c1.y + w2 * c2.y + w3 * c3.y;
            r.z = w0 * c0.z + w1 * c1.z + w2 * c2.z + w3 * c3.z;
            r.w = w0 * c0.w + w1 * c1.w + w2 * c2.w + w3 * c3.w;
            smB[i] = r;
        }
        __syncthreads();
        for (int job = wq; job < 2048; job += NWQ) {
            const int j   = job >> 1;
            const int bl0 = (job & 1) * 8;
            float acc[8];
#pragma unroll
            for (int i = 0; i < 8; ++i) acc[i] = 0.f;
            dot1(reinterpret_cast<const float4*>(Wc + (size_t)j * 2 * H),
                 smA + bl0 * H4, H4, 8, lane, acc);
            dot1(reinterpret_cast<const float4*>(Wc + (size_t)j * 2 * H) + H4,
                 smB + bl0 * H4, H4, 8, lane, acc);
            const float bcv = bc[j];
#pragma unroll
            for (int bb = 0; bb < 8; ++bb) {
                float s = wsum(acc[bb]);
                if (lane == bb) g_co[(hb0 + bl0 + bb) * H + j] = tanhf(s + bcv);
            }
        }
        sbar(nblk, bx, ++gen);

        // ---- P6: mel + gate projections ----
        for (int job = wq; job < 258; job += NWQ) {
            const int c   = job >> 1;
            const int bl0 = (job & 1) * 8;
            const int b0  = hb0 + bl0;
            float acc[8];
#pragma unroll
            for (int i = 0; i < 8; ++i) acc[i] = 0.f;
            const float4* wp = reinterpret_cast<const float4*>(
                (c < MEL) ? (Wp + (size_t)c * H) : Wg);
            dot1(wp, reinterpret_cast<const float4*>(g_co) + (size_t)b0 * H4,
                 H4, 8, lane, acc);
            const float bias = (c < MEL) ? bp[c] : bg[0];
#pragma unroll
            for (int bb = 0; bb < 8; ++bb) {
                float s = wsum(acc[bb]);
                if (lane == bb) {
                    const int b = b0 + bb;
                    const bool msk = step > lens[b];
                    if (c < MEL) {
                        const float val = s + bias;
                        g_decin[b * MEL + c] = val;
                        __stcs(&out[((size_t)b * TMEL + step) * MEL + c], msk ? 0.f : val);
                    } else {
                        __stcs(&out[OFF_GATE + (size_t)b * TMEL + step],
                               msk ? 1000.f : (s + bias));
                    }
                }
            }
        }
        sbar(nblk, bx, ++gen);
    }
}

// ---------------- host launch -------------------------------------------------
extern "C" void kernel_launch(void* const* d_in, const int* in_sizes, int n_in,
                              void* d_out, int out_size) {
    (void)in_sizes; (void)n_in; (void)out_size;
    int dev = 0;
    cudaGetDevice(&dev);
    int sms = 0;
    cudaDeviceGetAttribute(&sms, cudaDevAttrMultiProcessorCount, dev);
    if (sms <= 0) sms = 148;
    if (sms > 152) sms = 152;
    sms &= ~1;

    const int smem_bytes = 8192 * 16;         // 128 KB dynamic smem
    cudaFuncSetAttribute(decoder_kernel,
                         cudaFuncAttributeMaxDynamicSharedMemorySize, smem_bytes);

    decoder_kernel<<<sms, 512, smem_bytes>>>(
        (const float*)d_in[0],   // encoder_hidden [4,B,H]
        (const float*)d_in[1],   // encoder_outputs [B,TENC,H]
        (const int*)d_in[3],     // mel_spec_lens [B]   (d_in[2] = y, unused)
        (const float*)d_in[4],  (const float*)d_in[5],    // W_attn, b_attn
        (const float*)d_in[6],  (const float*)d_in[7],    // W_ih0, W_hh0
        (const float*)d_in[8],  (const float*)d_in[9],    // b_ih0, b_hh0
        (const float*)d_in[10], (const float*)d_in[11],   // W_ih1, W_hh1
        (const float*)d_in[12], (const float*)d_in[13],   // b_ih1, b_hh1
        (const float*)d_in[14], (const float*)d_in[15],   // Wc, bc
        (const float*)d_in[16], (const float*)d_in[17],   // Wp, bp
        (const float*)d_in[18], (const float*)d_in[19],   // Wg, bg
        (float*)d_out, sms);
}

// round 15
// speedup vs baseline: 1.1310x; 1.1310x over previous
#include <cuda_runtime.h>
#include <cuda_fp16.h>
#include <cstdint>

constexpr int B    = 32;
constexpr int H    = 1024;
constexpr int MEL  = 128;
constexpr int TENC = 512;
constexpr int TMEL = 400;
constexpr int H4   = H / 4;

constexpr size_t OFF_GATE = (size_t)B * TMEL * MEL;
constexpr size_t OFF_MASK = OFF_GATE + (size_t)B * TMEL;

// ---------------- device scratch (no allocations allowed) -------------------
__device__ float g_WT[(size_t)H * H];       // W_attn^T
__device__ __half g_ench[(size_t)B * TENC * H];   // fp16 enc copy, 33.5 MB
__device__ float g_h0[2][B * H];
__device__ float g_h1[2][B * H];
__device__ float g_decin[B * MEL];
__device__ float g_v[B * H];
__device__ float g_co[B * H];
// attention partials: 4 t-tiles of 128
__device__ float pm[4][B];
__device__ float pl[4][B];
__device__ float pctx[4][B * H];

// barriers
__device__ unsigned g_bar_arrive = 0;
__device__ volatile unsigned g_bar_gen = 0;
__device__ volatile unsigned g_arr[152 * 8];
__device__ volatile unsigned g_release;

// ---------------- helpers ----------------------------------------------------
__device__ __forceinline__ float wsum(float v) {
    v += __shfl_xor_sync(0xffffffffu, v, 16);
    v += __shfl_xor_sync(0xffffffffu, v, 8);
    v += __shfl_xor_sync(0xffffffffu, v, 4);
    v += __shfl_xor_sync(0xffffffffu, v, 2);
    v += __shfl_xor_sync(0xffffffffu, v, 1);
    return v;
}
__device__ __forceinline__ float dot4(float4 a, float4 b, float acc) {
    acc = fmaf(a.x, b.x, acc);
    acc = fmaf(a.y, b.y, acc);
    acc = fmaf(a.z, b.z, acc);
    acc = fmaf(a.w, b.w, acc);
    return acc;
}
__device__ __forceinline__ float sigmoidf_(float x) { return 1.f / (1.f + expf(-x)); }

__device__ __forceinline__ void abar(int nblk) {
    __syncthreads();
    if (threadIdx.x == 0) {
        __threadfence();
        unsigned gen = g_bar_gen;
        if (atomicAdd(&g_bar_arrive, 1u) == (unsigned)nblk - 1u) {
            g_bar_arrive = 0;
            __threadfence();
            g_bar_gen = gen + 1u;
        } else {
            while (g_bar_gen == gen) { __nanosleep(64); }
        }
        __threadfence();
    }
    __syncthreads();
}

// grid barrier: per-block arrive slots, block 0 scans, others poll one word.
__device__ __forceinline__ void sbar(int nblk, int bx, unsigned gen) {
    __syncthreads();
    if (threadIdx.x == 0) { __threadfence(); g_arr[bx * 8] = gen; }
    if (bx == 0) {
        if (threadIdx.x < 32) {
            for (;;) {
                bool ok = true;
                for (int i = threadIdx.x; i < nblk; i += 32)
                    ok &= (g_arr[i * 8] >= gen);
                if (__all_sync(0xffffffffu, ok)) break;
                __nanosleep(32);
            }
            if (threadIdx.x == 0) { __threadfence(); g_release = gen; }
        }
    } else if (threadIdx.x == 0) {
        while (g_release < gen) { __nanosleep(64); }
        __threadfence();
    }
    __syncthreads();
}

__device__ __forceinline__ void stage(float4* dst, const float* src, int n4, int tid) {
    const float4* s = reinterpret_cast<const float4*>(src);
    for (int i = tid; i < n4; i += 512) dst[i] = s[i];
}

// 3-row dot vs 8 batches (acts in smem), weight prefetch depth 2.
__device__ __forceinline__ void dot3(
    const float4* __restrict__ w0, const float4* __restrict__ w1,
    const float4* __restrict__ w2,
    const float4* __restrict__ actb, int bstride4, int nIt, int lane,
    float A0[8], float A1[8], float A2[8])
{
    float4 c0 = w0[lane], c1 = w1[lane], c2 = w2[lane];
    float4 n0 = c0, n1 = c1, n2 = c2;
    if (nIt > 1) { n0 = w0[lane + 32]; n1 = w1[lane + 32]; n2 = w2[lane + 32]; }
    for (int i = 0; i < nIt; ++i) {
        float4 p0 = n0, p1 = n1, p2 = n2;
        if (i + 2 < nIt) {
            p0 = w0[lane + (i + 2) * 32];
            p1 = w1[lane + (i + 2) * 32];
            p2 = w2[lane + (i + 2) * 32];
        }
        const float4* a = actb + i * 32 + lane;
#pragma unroll
        for (int bb = 0; bb < 8; ++bb) {
            float4 av = a[bb * bstride4];
            A0[bb] = dot4(c0, av, A0[bb]);
            A1[bb] = dot4(c1, av, A1[bb]);
            A2[bb] = dot4(c2, av, A2[bb]);
        }
        c0 = n0; c1 = n1; c2 = n2;
        n0 = p0; n1 = p1; n2 = p2;
    }
}

// 1-row dot vs 8 batches, prefetch depth 2.
__device__ __forceinline__ void dot1(
    const float4* __restrict__ w,
    const float4* __restrict__ actb, int bstride4, int nIt, int lane,
    float A[8])
{
    float4 c = w[lane];
    float4 n = c;
    if (nIt > 1) n = w[lane + 32];
    for (int i = 0; i < nIt; ++i) {
        float4 p = n;
        if (i + 2 < nIt) p = w[lane + (i + 2) * 32];
        const float4* a = actb + i * 32 + lane;
#pragma unroll
        for (int bb = 0; bb < 8; ++bb)
            A[bb] = dot4(c, a[bb * bstride4], A[bb]);
        c = n; n = p;
    }
}

// merged GRU cell: acts from smem, direct state write
__device__ __forceinline__ void gru_sm(
    int j, int bl0, int lane, int hb0,
    const float4* __restrict__ smX, int XD,
    const float4* __restrict__ smH, const float* __restrict__ smHf,
    float* __restrict__ hnew,
    const float* __restrict__ Wih, const float* __restrict__ Whh,
    const float* __restrict__ bih, const float* __restrict__ bhh)
{
    const int XD4 = XD >> 2, nItX = XD4 >> 5;
    float ar[8], az[8], ani[8], anh[8];
#pragma unroll
    for (int i = 0; i < 8; ++i) { ar[i] = 0.f; az[i] = 0.f; ani[i] = 0.f; anh[i] = 0.f; }

    dot3(reinterpret_cast<const float4*>(Wih + (size_t)j * XD),
         reinterpret_cast<const float4*>(Wih + (size_t)(H + j) * XD),
         reinterpret_cast<const float4*>(Wih + (size_t)(2 * H + j) * XD),
         smX + bl0 * XD4, XD4, nItX, lane, ar, az, ani);
    dot3(reinterpret_cast<const float4*>(Whh + (size_t)j * H),
         reinterpret_cast<const float4*>(Whh + (size_t)(H + j) * H),
         reinterpret_cast<const float4*>(Whh + (size_t)(2 * H + j) * H),
         smH + bl0 * H4, H4, 8, lane, ar, az, anh);

    const float br  = bih[j] + bhh[j];
    const float bz  = bih[H + j] + bhh[H + j];
    const float bni = bih[2 * H + j];
    const float bnh = bhh[2 * H + j];
#pragma unroll
    for (int bb = 0; bb < 8; ++bb) {
        float r  = wsum(ar[bb]);
        float z  = wsum(az[bb]);
        float ni = wsum(ani[bb]);
        float nh = wsum(anh[bb]);
        if (lane == bb) {
            float rr = sigmoidf_(r + br);
            float zz = sigmoidf_(z + bz);
            float hp = smHf[(bl0 + bb) * H + j];
            float nn = tanhf(ni + bni + rr * (nh + bnh));
            hnew[(hb0 + bl0 + bb) * H + j] = (1.f - zz) * nn + zz * hp;
        }
    }
}

// ---------------- main persistent kernel -------------------------------------
__global__ void __launch_bounds__(512, 1)
decoder_kernel(const float* __restrict__ enc_hidden,
               const float* __restrict__ enc_out,
               const int*   __restrict__ lens,
               const float* __restrict__ W_attn, const float* __restrict__ b_attn,
               const float* __restrict__ Wih0, const float* __restrict__ Whh0,
               const float* __restrict__ bih0, const float* __restrict__ bhh0,
               const float* __restrict__ Wih1, const float* __restrict__ Whh1,
               const float* __restrict__ bih1, const float* __restrict__ bhh1,
               const float* __restrict__ Wc,   const float* __restrict__ bc,
               const float* __restrict__ Wp,   const float* __restrict__ bp,
               const float* __restrict__ Wg,   const float* __restrict__ bg,
               float* __restrict__ out, int nblk) {
    extern __shared__ float4 sm4[];
    float4* smA = sm4;                 // 64 KB
    float4* smB = sm4 + 4096;          // 64 KB
    const float* smBf = reinterpret_cast<const float*>(smB);
    float* smV = reinterpret_cast<float*>(sm4);   // ATT: v[b] (4 KB)

    __shared__ float smS[16];          // subtile scores
    __shared__ float smP[16];          // subtile exp weights
    __shared__ float smW[64];          // per-batch combine weights (4 tiles x 16)

    const int tid  = threadIdx.x;
    const int lane = tid & 31;
    const int wid  = tid >> 5;
    const int bx   = blockIdx.x;
    const int half = bx & 1;
    const int bq   = bx >> 1;
    const int nbh  = nblk >> 1;
    const int wq   = bq * 16 + wid;
    const int NWQ  = nbh * 16;
    const int hb0  = half * 16;
    const int gtid = bx * blockDim.x + tid;
    const int gsz  = nblk * blockDim.x;

    // ================= init =================
    for (int i = gtid; i < H * H; i += gsz) {
        int c = i >> 10, j = i & (H - 1);
        g_WT[i] = W_attn[(size_t)j * H + c];
    }
    for (size_t i = gtid; i < (size_t)B * TENC * H; i += gsz)
        g_ench[i] = __float2half(enc_out[i]);
    for (int i = gtid; i < B * H; i += gsz) {
        g_h0[0][i] = enc_hidden[i];
        g_h1[0][i] = enc_hidden[B * H + i];
    }
    for (int i = gtid; i < B * MEL; i += gsz) g_decin[i] = 0.f;
    for (int i = gtid; i < B * TMEL; i += gsz) {
        int b = i / TMEL, t = i - b * TMEL;
        out[OFF_MASK + i] = (t > lens[b]) ? 1.f : 0.f;
    }
    for (int i = gtid; i < 152 * 8; i += gsz) g_arr[i] = 0u;
    if (gtid == 0) g_release = 0u;
    abar(nblk);

    unsigned gen = 0;

    // ================= 400 autoregressive steps =================
    for (int step = 0; step < TMEL; ++step) {
        const int cur = step & 1, nxt = cur ^ 1;

        // ---- GRU layer 0 ----
        stage(smA, g_decin + hb0 * MEL, 16 * MEL / 4, tid);
        stage(smB, g_h0[cur] + hb0 * H, 4096, tid);
        __syncthreads();
        for (int job = wq; job < 2048; job += NWQ)
            gru_sm(job >> 1, (job & 1) * 8, lane, hb0, smA, MEL, smB, smBf,
                   g_h0[nxt], Wih0, Whh0, bih0, bhh0);
        sbar(nblk, bx, ++gen);

        // ---- GRU layer 1 ----
        stage(smA, g_h0[nxt] + hb0 * H, 4096, tid);
        stage(smB, g_h1[cur] + hb0 * H, 4096, tid);
        __syncthreads();
        for (int job = wq; job < 2048; job += NWQ)
            gru_sm(job >> 1, (job & 1) * 8, lane, hb0, smA, H, smB, smBf,
                   g_h1[nxt], Wih1, Whh1, bih1, bhh1);
        sbar(nblk, bx, ++gen);

        // ---- Pv: v = W_attn^T h1 (bias drops in softmax) ----
        stage(smA, g_h1[nxt] + hb0 * H, 4096, tid);
        __syncthreads();
        for (int job = wq; job < 2048; job += NWQ) {
            const int c   = job >> 1;
            const int bl0 = (job & 1) * 8;
            float acc[8];
#pragma unroll
            for (int i = 0; i < 8; ++i) acc[i] = 0.f;
            dot1(reinterpret_cast<const float4*>(g_WT + (size_t)c * H),
                 smA + bl0 * H4, H4, 8, lane, acc);
#pragma unroll
            for (int bb = 0; bb < 8; ++bb) {
                float s = wsum(acc[bb]);
                if (lane == bb) g_v[(hb0 + bl0 + bb) * H + c] = s;
            }
        }
        sbar(nblk, bx, ++gen);

        // ---- ATT: fused scores+softmax+context over fp16 enc (L2-resident) ----
        for (int job = bx; job < 128; job += nblk) {
            const int b    = job >> 2;
            const int tile = job & 3;
            const int t0   = tile * 128;
            __syncthreads();
            for (int i = tid; i < 1024; i += 512) smV[i] = g_v[b * H + i];
            __syncthreads();

            float m_run = -1e30f, l_run = 0.f;
            float a0 = 0.f, a1 = 0.f;
            const int hc = wid * 64;

            for (int sub = 0; sub < 8; ++sub) {
                const int ts = t0 + sub * 16;
                // scores: warp wid computes t = ts + wid
                {
                    const __half2* er = reinterpret_cast<const __half2*>(
                        g_ench + ((size_t)b * TENC + ts + wid) * H);
                    const float4* v4 = reinterpret_cast<const float4*>(smV);
                    float acc = 0.f;
#pragma unroll
                    for (int k = 0; k < 8; ++k) {
                        const int idx = k * 32 + lane;
                        float2 f01 = __half22float2(er[2 * idx]);
                        float2 f23 = __half22float2(er[2 * idx + 1]);
                        float4 vv = v4[idx];
                        acc = fmaf(vv.x, f01.x, fmaf(vv.y, f01.y,
                              fmaf(vv.z, f23.x, fmaf(vv.w, f23.y, acc))));
                    }
                    acc = wsum(acc);
                    if (lane == 0) smS[wid] = acc;
                }
                __syncthreads();
                float msub = -1e30f;
#pragma unroll
                for (int i = 0; i < 16; ++i) msub = fmaxf(msub, smS[i]);
                const float m_new = fmaxf(m_run, msub);
                if (lane == 0) smP[wid] = expf(smS[wid] - m_new);
                const float scale = expf(m_run - m_new);
                __syncthreads();
                // context accumulate for this warp's 64-wide h-chunk
                a0 *= scale; a1 *= scale;
                float lsub = 0.f;
                const __half* eb = g_ench + ((size_t)b * TENC + ts) * H + hc + lane;
#pragma unroll 4
                for (int t = 0; t < 16; ++t) {
                    float p = smP[t];
                    lsub += p;
                    a0 = fmaf(p, __half2float(eb[(size_t)t * H]), a0);
                    a1 = fmaf(p, __half2float(eb[(size_t)t * H + 32]), a1);
                }
                l_run = l_run * scale + lsub;
                m_run = m_new;
                __syncthreads();
            }
            // write tile partials (unnormalized)
            pctx[tile][b * H + hc + lane]      = a0;
            pctx[tile][b * H + hc + 32 + lane] = a1;
            if (tid == 0) { pm[tile][b] = m_run; pl[tile][b] = l_run; }
        }
        sbar(nblk, bx, ++gen);

        const float* h1n = g_h1[nxt];

        // ---- P5: combine ctx tiles into smB, stage h1 into smA, then GEMM ----
        if (tid < 16) {
            const int b = hb0 + tid;
            float m0 = pm[0][b], m1 = pm[1][b], m2 = pm[2][b], m3 = pm[3][b];
            float M = fmaxf(fmaxf(m0, m1), fmaxf(m2, m3));
            float e0 = expf(m0 - M), e1 = expf(m1 - M);
            float e2 = expf(m2 - M), e3 = expf(m3 - M);
            float invL = 1.f / (e0 * pl[0][b] + e1 * pl[1][b] +
                                e2 * pl[2][b] + e3 * pl[3][b]);
            smW[tid]      = e0 * invL;
            smW[16 + tid] = e1 * invL;
            smW[32 + tid] = e2 * invL;
            smW[48 + tid] = e3 * invL;
        }
        stage(smA, h1n + hb0 * H, 4096, tid);
        __syncthreads();
        for (int i = tid; i < 4096; i += 512) {
            const int bl = i >> 8;
            const size_t off = (size_t)(hb0 + bl) * 256 + (i & 255);
            float w0 = smW[bl], w1 = smW[16 + bl], w2 = smW[32 + bl], w3 = smW[48 + bl];
            float4 c0 = reinterpret_cast<const float4*>(pctx[0])[off];
            float4 c1 = reinterpret_cast<const float4*>(pctx[1])[off];
            float4 c2 = reinterpret_cast<const float4*>(pctx[2])[off];
            float4 c3 = reinterpret_cast<const float4*>(pctx[3])[off];
            float4 r;
            r.x = w0 * c0.x + w1 * c1.x + w2 * c2.x + w3 * c3.x;
            r.y = w0 * c0.y + w1 * c1.y + w2 * c2.y + w3 * c3.y;
            r.z = w0 * c0.z + w1 * c1.z + w2 * c2.z + w3 * c3.z;
            r.w = w0 * c0.w + w1 * c1.w + w2 * c2.w + w3 * c3.w;
            smB[i] = r;
        }
        __syncthreads();
        for (int job = wq; job < 2048; job += NWQ) {
            const int j   = job >> 1;
            const int bl0 = (job & 1) * 8;
            float acc[8];
#pragma unroll
            for (int i = 0; i < 8; ++i) acc[i] = 0.f;
            dot1(reinterpret_cast<const float4*>(Wc + (size_t)j * 2 * H),
                 smA + bl0 * H4, H4, 8, lane, acc);
            dot1(reinterpret_cast<const float4*>(Wc + (size_t)j * 2 * H) + H4,
                 smB + bl0 * H4, H4, 8, lane, acc);
            const float bcv = bc[j];
#pragma unroll
            for (int bb = 0; bb < 8; ++bb) {
                float s = wsum(acc[bb]);
                if (lane == bb) g_co[(hb0 + bl0 + bb) * H + j] = tanhf(s + bcv);
            }
        }
        sbar(nblk, bx, ++gen);

        // ---- P6: mel + gate projections ----
        for (int job = wq; job < 258; job += NWQ) {
            const int c   = job >> 1;
            const int bl0 = (job & 1) * 8;
            const int b0  = hb0 + bl0;
            float acc[8];
#pragma unroll
            for (int i = 0; i < 8; ++i) acc[i] = 0.f;
            const float4* wp = reinterpret_cast<const float4*>(
                (c < MEL) ? (Wp + (size_t)c * H) : Wg);
            dot1(wp, reinterpret_cast<const float4*>(g_co) + (size_t)b0 * H4,
                 H4, 8, lane, acc);
            const float bias = (c < MEL) ? bp[c] : bg[0];
#pragma unroll
            for (int bb = 0; bb < 8; ++bb) {
                float s = wsum(acc[bb]);
                if (lane == bb) {
                    const int b = b0 + bb;
                    const bool msk = step > lens[b];
                    if (c < MEL) {
                        const float val = s + bias;
                        g_decin[b * MEL + c] = val;
                        __stcs(&out[((size_t)b * TMEL + step) * MEL + c], msk ? 0.f : val);
                    } else {
                        __stcs(&out[OFF_GATE + (size_t)b * TMEL + step],
                               msk ? 1000.f : (s + bias));
                    }
                }
            }
        }
        sbar(nblk, bx, ++gen);
    }
}

// ---------------- host launch -------------------------------------------------
extern "C" void kernel_launch(void* const* d_in, const int* in_sizes, int n_in,
                              void* d_out, int out_size) {
    (void)in_sizes; (void)n_in; (void)out_size;
    int dev = 0;
    cudaGetDevice(&dev);
    int sms = 0;
    cudaDeviceGetAttribute(&sms, cudaDevAttrMultiProcessorCount, dev);
    if (sms <= 0) sms = 148;
    if (sms > 152) sms = 152;
    sms &= ~1;

    const int smem_bytes = 8192 * 16;         // 128 KB dynamic smem
    cudaFuncSetAttribute(decoder_kernel,
                         cudaFuncAttributeMaxDynamicSharedMemorySize, smem_bytes);

    decoder_kernel<<<sms, 512, smem_bytes>>>(
        (const float*)d_in[0],   // encoder_hidden [4,B,H]
        (const float*)d_in[1],   // encoder_outputs [B,TENC,H]
        (const int*)d_in[3],     // mel_spec_lens [B]   (d_in[2] = y, unused)
        (const float*)d_in[4],  (const float*)d_in[5],    // W_attn, b_attn
        (const float*)d_in[6],  (const float*)d_in[7],    // W_ih0, W_hh0
        (const float*)d_in[8],  (const float*)d_in[9],    // b_ih0, b_hh0
        (const float*)d_in[10], (const float*)d_in[11],   // W_ih1, W_hh1
        (const float*)d_in[12], (const float*)d_in[13],   // b_ih1, b_hh1
        (const float*)d_in[14], (const float*)d_in[15],   // Wc, bc
        (const float*)d_in[16], (const float*)d_in[17],   // Wp, bp
        (const float*)d_in[18], (const float*)d_in[19],   // Wg, bg
        (float*)d_out, sms);
}

// round 16
// speedup vs baseline: 1.3184x; 1.1658x over previous
#include <cuda_runtime.h>
#include <cuda_fp16.h>
#include <cstdint>

constexpr int B    = 32;
constexpr int H    = 1024;
constexpr int MEL  = 128;
constexpr int TENC = 512;
constexpr int TMEL = 400;
constexpr int H4   = H / 4;

constexpr size_t OFF_GATE = (size_t)B * TMEL * MEL;
constexpr size_t OFF_MASK = OFF_GATE + (size_t)B * TMEL;

// ---------------- device scratch (no allocations allowed) -------------------
__device__ float g_WT[(size_t)H * H];       // W_attn^T
__device__ __half g_ench[(size_t)B * TENC * H];   // fp16 enc copy (orig batch idx)
__device__ float g_h0[2][B * H];            // slot-indexed
__device__ float g_h1[2][B * H];
__device__ float g_decin[B * MEL];
__device__ float g_v[B * H];
__device__ float g_co[B * H];
__device__ int   g_perm[B];                 // slot -> original batch
// attention partials: 4 t-tiles of 128 (slot-indexed)
__device__ float pm[4][B];
__device__ float pl[4][B];
__device__ float pctx[4][B * H];

// barriers
__device__ unsigned g_bar_arrive = 0;
__device__ volatile unsigned g_bar_gen = 0;
__device__ volatile unsigned g_arr[152 * 8];
__device__ volatile unsigned g_release;

// ---------------- helpers ----------------------------------------------------
__device__ __forceinline__ float wsum(float v) {
    v += __shfl_xor_sync(0xffffffffu, v, 16);
    v += __shfl_xor_sync(0xffffffffu, v, 8);
    v += __shfl_xor_sync(0xffffffffu, v, 4);
    v += __shfl_xor_sync(0xffffffffu, v, 2);
    v += __shfl_xor_sync(0xffffffffu, v, 1);
    return v;
}
__device__ __forceinline__ float dot4(float4 a, float4 b, float acc) {
    acc = fmaf(a.x, b.x, acc);
    acc = fmaf(a.y, b.y, acc);
    acc = fmaf(a.z, b.z, acc);
    acc = fmaf(a.w, b.w, acc);
    return acc;
}
__device__ __forceinline__ float sigmoidf_(float x) { return 1.f / (1.f + expf(-x)); }

__device__ __forceinline__ void abar(int nblk) {
    __syncthreads();
    if (threadIdx.x == 0) {
        __threadfence();
        unsigned gen = g_bar_gen;
        if (atomicAdd(&g_bar_arrive, 1u) == (unsigned)nblk - 1u) {
            g_bar_arrive = 0;
            __threadfence();
            g_bar_gen = gen + 1u;
        } else {
            while (g_bar_gen == gen) { __nanosleep(64); }
        }
        __threadfence();
    }
    __syncthreads();
}

__device__ __forceinline__ void sbar(int nblk, int bx, unsigned gen) {
    __syncthreads();
    if (threadIdx.x == 0) { __threadfence(); g_arr[bx * 8] = gen; }
    if (bx == 0) {
        if (threadIdx.x < 32) {
            for (;;) {
                bool ok = true;
                for (int i = threadIdx.x; i < nblk; i += 32)
                    ok &= (g_arr[i * 8] >= gen);
                if (__all_sync(0xffffffffu, ok)) break;
                __nanosleep(32);
            }
            if (threadIdx.x == 0) { __threadfence(); g_release = gen; }
        }
    } else if (threadIdx.x == 0) {
        while (g_release < gen) { __nanosleep(64); }
        __threadfence();
    }
    __syncthreads();
}

__device__ __forceinline__ void stage(float4* dst, const float* src, int n4, int tid) {
    const float4* s = reinterpret_cast<const float4*>(src);
    for (int i = tid; i < n4; i += 512) dst[i] = s[i];
}

// 3-row dot vs 8 batches (acts in smem), weight prefetch depth 2.
__device__ __forceinline__ void dot3(
    const float4* __restrict__ w0, const float4* __restrict__ w1,
    const float4* __restrict__ w2,
    const float4* __restrict__ actb, int bstride4, int nIt, int lane,
    float A0[8], float A1[8], float A2[8])
{
    float4 c0 = w0[lane], c1 = w1[lane], c2 = w2[lane];
    float4 n0 = c0, n1 = c1, n2 = c2;
    if (nIt > 1) { n0 = w0[lane + 32]; n1 = w1[lane + 32]; n2 = w2[lane + 32]; }
    for (int i = 0; i < nIt; ++i) {
        float4 p0 = n0, p1 = n1, p2 = n2;
        if (i + 2 < nIt) {
            p0 = w0[lane + (i + 2) * 32];
            p1 = w1[lane + (i + 2) * 32];
            p2 = w2[lane + (i + 2) * 32];
        }
        const float4* a = actb + i * 32 + lane;
#pragma unroll
        for (int bb = 0; bb < 8; ++bb) {
            float4 av = a[bb * bstride4];
            A0[bb] = dot4(c0, av, A0[bb]);
            A1[bb] = dot4(c1, av, A1[bb]);
            A2[bb] = dot4(c2, av, A2[bb]);
        }
        c0 = n0; c1 = n1; c2 = n2;
        n0 = p0; n1 = p1; n2 = p2;
    }
}

// 1-row dot vs 8 batches, prefetch depth 2.
__device__ __forceinline__ void dot1(
    const float4* __restrict__ w,
    const float4* __restrict__ actb, int bstride4, int nIt, int lane,
    float A[8])
{
    float4 c = w[lane];
    float4 n = c;
    if (nIt > 1) n = w[lane + 32];
    for (int i = 0; i < nIt; ++i) {
        float4 p = n;
        if (i + 2 < nIt) p = w[lane + (i + 2) * 32];
        const float4* a = actb + i * 32 + lane;
#pragma unroll
        for (int bb = 0; bb < 8; ++bb)
            A[bb] = dot4(c, a[bb * bstride4], A[bb]);
        c = n; n = p;
    }
}

// merged GRU cell for one group of 8 slots, acts in smem
__device__ __forceinline__ void gru_sm(
    int j, int lane, int s0,
    const float4* __restrict__ smX, int XD4, int nItX,
    const float4* __restrict__ smH, const float* __restrict__ smHf,
    float* __restrict__ hnew,
    const float* __restrict__ Wih, const float* __restrict__ Whh,
    const float* __restrict__ bih, const float* __restrict__ bhh)
{
    const int XD = XD4 << 2;
    float ar[8], az[8], ani[8], anh[8];
#pragma unroll
    for (int i = 0; i < 8; ++i) { ar[i] = 0.f; az[i] = 0.f; ani[i] = 0.f; anh[i] = 0.f; }

    dot3(reinterpret_cast<const float4*>(Wih + (size_t)j * XD),
         reinterpret_cast<const float4*>(Wih + (size_t)(H + j) * XD),
         reinterpret_cast<const float4*>(Wih + (size_t)(2 * H + j) * XD),
         smX, XD4, nItX, lane, ar, az, ani);
    dot3(reinterpret_cast<const float4*>(Whh + (size_t)j * H),
         reinterpret_cast<const float4*>(Whh + (size_t)(H + j) * H),
         reinterpret_cast<const float4*>(Whh + (size_t)(2 * H + j) * H),
         smH, H4, 8, lane, ar, az, anh);

    const float br  = bih[j] + bhh[j];
    const float bz  = bih[H + j] + bhh[H + j];
    const float bni = bih[2 * H + j];
    const float bnh = bhh[2 * H + j];
#pragma unroll
    for (int bb = 0; bb < 8; ++bb) {
        float r  = wsum(ar[bb]);
        float z  = wsum(az[bb]);
        float ni = wsum(ani[bb]);
        float nh = wsum(anh[bb]);
        if (lane == bb) {
            float rr = sigmoidf_(r + br);
            float zz = sigmoidf_(z + bz);
            float hp = smHf[bb * H + j];
            float nn = tanhf(ni + bni + rr * (nh + bnh));
            hnew[(s0 + bb) * H + j] = (1.f - zz) * nn + zz * hp;
        }
    }
}

// ---------------- main persistent kernel -------------------------------------
__global__ void __launch_bounds__(512, 1)
decoder_kernel(const float* __restrict__ enc_hidden,
               const float* __restrict__ enc_out,
               const int*   __restrict__ lens,
               const float* __restrict__ W_attn, const float* __restrict__ b_attn,
               const float* __restrict__ Wih0, const float* __restrict__ Whh0,
               const float* __restrict__ bih0, const float* __restrict__ bhh0,
               const float* __restrict__ Wih1, const float* __restrict__ Whh1,
               const float* __restrict__ bih1, const float* __restrict__ bhh1,
               const float* __restrict__ Wc,   const float* __restrict__ bc,
               const float* __restrict__ Wp,   const float* __restrict__ bp,
               const float* __restrict__ Wg,   const float* __restrict__ bg,
               float* __restrict__ out, int nblk) {
    extern __shared__ float4 sm4[];
    float4* smA = sm4;                 // 32 KB (2048 f4)
    float4* smB = sm4 + 2048;          // 32 KB
    const float* smBf = reinterpret_cast<const float*>(smB);
    float* smV = reinterpret_cast<float*>(sm4);   // ATT: v[slot] (4 KB)

    __shared__ float smS[16];
    __shared__ float smP[16];
    __shared__ float smW[32];          // 4 tiles x 8 slots

    const int tid  = threadIdx.x;
    const int lane = tid & 31;
    const int wid  = tid >> 5;
    const int bx   = blockIdx.x;
    const int gtid = bx * blockDim.x + tid;
    const int gsz  = nblk * blockDim.x;

    // ---- sort batches by lens (every thread, O(32^2)) ----
    int lensv[B];
#pragma unroll
    for (int b = 0; b < B; ++b) lensv[b] = lens[b];
    int permL[B];
#pragma unroll
    for (int b = 0; b < B; ++b) {
        int r = 0;
#pragma unroll
        for (int b2 = 0; b2 < B; ++b2)
            r += (lensv[b2] < lensv[b]) || (lensv[b2] == lensv[b] && b2 < b);
        permL[r] = b;
    }
    const int gmax0 = lensv[permL[7]];
    const int gmax1 = lensv[permL[15]];
    const int gmax2 = lensv[permL[23]];
    const int gmax3 = lensv[permL[31]];

    // ================= init =================
    if (gtid < B) g_perm[gtid] = permL[gtid];
    for (int i = gtid; i < H * H; i += gsz) {
        int c = i >> 10, j = i & (H - 1);
        g_WT[i] = W_attn[(size_t)j * H + c];
    }
    for (size_t i = gtid; i < (size_t)B * TENC * H; i += gsz)
        g_ench[i] = __float2half(enc_out[i]);
    for (int i = gtid; i < B * H; i += gsz) {
        int slot = i >> 10, j = i & (H - 1);
        int bo = permL[slot];
        g_h0[0][i] = enc_hidden[bo * H + j];
        g_h1[0][i] = enc_hidden[B * H + bo * H + j];
    }
    for (int i = gtid; i < B * MEL; i += gsz) g_decin[i] = 0.f;
    // masks + masked-output prefill (constants for t > lens[b])
    for (int i = gtid; i < B * TMEL; i += gsz) {
        int b = i / TMEL, t = i - b * TMEL;
        bool msk = t > lensv[b];
        out[OFF_MASK + i] = msk ? 1.f : 0.f;
        if (msk) out[OFF_GATE + i] = 1000.f;
    }
    for (size_t i = gtid; i < (size_t)B * TMEL * MEL; i += gsz) {
        int b = (int)(i / (TMEL * MEL));
        int t = (int)((i / MEL) % TMEL);
        if (t > lensv[b]) out[i] = 0.f;
    }
    for (int i = gtid; i < 152 * 8; i += gsz) g_arr[i] = 0u;
    if (gtid == 0) g_release = 0u;
    abar(nblk);

    unsigned gen = 0;

    // ================= autoregressive steps (only while any batch live) ======
    const int maxstep = (gmax3 < TMEL - 1) ? gmax3 : (TMEL - 1);
    for (int step = 0; step <= maxstep; ++step) {
        const int cur = step & 1, nxt = cur ^ 1;

        // active-group suffix
        const int fa = (step <= gmax0) ? 0 : (step <= gmax1) ? 1
                      : (step <= gmax2) ? 2 : 3;
        const int A    = 4 - fa;
        const int gidx = bx % A;
        const int g    = fa + gidx;
        const int s0   = g * 8;
        const int nbg  = (nblk - gidx - 1) / A + 1;
        const int wg   = (bx / A) * 16 + wid;
        const int NWG  = nbg * 16;

        // ---- GRU layer 0 ----
        stage(smA, g_decin + s0 * MEL, 256, tid);
        stage(smB, g_h0[cur] + s0 * H, 2048, tid);
        __syncthreads();
        for (int j = wg; j < H; j += NWG)
            gru_sm(j, lane, s0, smA, MEL / 4, 1, smB, smBf,
                   g_h0[nxt], Wih0, Whh0, bih0, bhh0);
        sbar(nblk, bx, ++gen);

        // ---- GRU layer 1 ----
        stage(smA, g_h0[nxt] + s0 * H, 2048, tid);
        stage(smB, g_h1[cur] + s0 * H, 2048, tid);
        __syncthreads();
        for (int j = wg; j < H; j += NWG)
            gru_sm(j, lane, s0, smA, H4, 8, smB, smBf,
                   g_h1[nxt], Wih1, Whh1, bih1, bhh1);
        sbar(nblk, bx, ++gen);

        // ---- Pv: v = W_attn^T h1 (bias drops in softmax) ----
        stage(smA, g_h1[nxt] + s0 * H, 2048, tid);
        __syncthreads();
        for (int c = wg; c < H; c += NWG) {
            float acc[8];
#pragma unroll
            for (int i = 0; i < 8; ++i) acc[i] = 0.f;
            dot1(reinterpret_cast<const float4*>(g_WT + (size_t)c * H),
                 smA, H4, 8, lane, acc);
#pragma unroll
            for (int bb = 0; bb < 8; ++bb) {
                float s = wsum(acc[bb]);
                if (lane == bb) g_v[(s0 + bb) * H + c] = s;
            }
        }
        sbar(nblk, bx, ++gen);

        // ---- ATT: fused scores+softmax+context over fp16 enc, active slots --
        const int nAct = (4 - fa) * 8;
        for (int job = bx; job < nAct * 4; job += nblk) {
            const int slot = fa * 8 + (job >> 2);
            const int bo   = g_perm[slot];
            const int tile = job & 3;
            const int t0   = tile * 128;
            __syncthreads();
            for (int i = tid; i < 1024; i += 512) smV[i] = g_v[slot * H + i];
            __syncthreads();

            float m_run = -1e30f, l_run = 0.f;
            float a0 = 0.f, a1 = 0.f;
            const int hc = wid * 64;

            for (int sub = 0; sub < 8; ++sub) {
                const int ts = t0 + sub * 16;
                {
                    const __half2* er = reinterpret_cast<const __half2*>(
                        g_ench + ((size_t)bo * TENC + ts + wid) * H);
                    const float4* v4 = reinterpret_cast<const float4*>(smV);
                    float acc = 0.f;
#pragma unroll
                    for (int k = 0; k < 8; ++k) {
                        const int idx = k * 32 + lane;
                        float2 f01 = __half22float2(er[2 * idx]);
                        float2 f23 = __half22float2(er[2 * idx + 1]);
                        float4 vv = v4[idx];
                        acc = fmaf(vv.x, f01.x, fmaf(vv.y, f01.y,
                              fmaf(vv.z, f23.x, fmaf(vv.w, f23.y, acc))));
                    }
                    acc = wsum(acc);
                    if (lane == 0) smS[wid] = acc;
                }
                __syncthreads();
                float msub = -1e30f;
#pragma unroll
                for (int i = 0; i < 16; ++i) msub = fmaxf(msub, smS[i]);
                const float m_new = fmaxf(m_run, msub);
                if (lane == 0) smP[wid] = expf(smS[wid] - m_new);
                const float scale = expf(m_run - m_new);
                __syncthreads();
                a0 *= scale; a1 *= scale;
                float lsub = 0.f;
                const __half* eb = g_ench + ((size_t)bo * TENC + ts) * H + hc + lane;
#pragma unroll 4
                for (int t = 0; t < 16; ++t) {
                    float p = smP[t];
                    lsub += p;
                    a0 = fmaf(p, __half2float(eb[(size_t)t * H]), a0);
                    a1 = fmaf(p, __half2float(eb[(size_t)t * H + 32]), a1);
                }
                l_run = l_run * scale + lsub;
                m_run = m_new;
                __syncthreads();
            }
            pctx[tile][slot * H + hc + lane]      = a0;
            pctx[tile][slot * H + hc + 32 + lane] = a1;
            if (tid == 0) { pm[tile][slot] = m_run; pl[tile][slot] = l_run; }
        }
        sbar(nblk, bx, ++gen);

        const float* h1n = g_h1[nxt];

        // ---- P5: combine ctx tiles + [h1; ctx] GEMM ----
        if (tid < 8) {
            const int slot = s0 + tid;
            float m0 = pm[0][slot], m1 = pm[1][slot];
            float m2 = pm[2][slot], m3 = pm[3][slot];
            float M = fmaxf(fmaxf(m0, m1), fmaxf(m2, m3));
            float e0 = expf(m0 - M), e1 = expf(m1 - M);
            float e2 = expf(m2 - M), e3 = expf(m3 - M);
            float invL = 1.f / (e0 * pl[0][slot] + e1 * pl[1][slot] +
                                e2 * pl[2][slot] + e3 * pl[3][slot]);
            smW[tid]      = e0 * invL;
            smW[8 + tid]  = e1 * invL;
            smW[16 + tid] = e2 * invL;
            smW[24 + tid] = e3 * invL;
        }
        stage(smA, h1n + s0 * H, 2048, tid);
        __syncthreads();
        for (int i = tid; i < 2048; i += 512) {
            const int bl = i >> 8;
            const size_t off = (size_t)(s0 + bl) * 256 + (i & 255);
            float w0 = smW[bl], w1 = smW[8 + bl], w2 = smW[16 + bl], w3 = smW[24 + bl];
            float4 c0 = reinterpret_cast<const float4*>(pctx[0])[off];
            float4 c1 = reinterpret_cast<const float4*>(pctx[1])[off];
            float4 c2 = reinterpret_cast<const float4*>(pctx[2])[off];
            float4 c3 = reinterpret_cast<const float4*>(pctx[3])[off];
            float4 r;
            r.x = w0 * c0.x + w1 * c1.x + w2 * c2.x + w3 * c3.x;
            r.y = w0 * c0.y + w1 * c1.y + w2 * c2.y + w3 * c3.y;
            r.z = w0 * c0.z + w1 * c1.z + w2 * c2.z + w3 * c3.z;
            r.w = w0 * c0.w + w1 * c1.w + w2 * c2.w + w3 * c3.w;
            smB[i] = r;
        }
        __syncthreads();
        for (int j = wg; j < H; j += NWG) {
            float acc[8];
#pragma unroll
            for (int i = 0; i < 8; ++i) acc[i] = 0.f;
            dot1(reinterpret_cast<const float4*>(Wc + (size_t)j * 2 * H),
                 smA, H4, 8, lane, acc);
            dot1(reinterpret_cast<const float4*>(Wc + (size_t)j * 2 * H) + H4,
                 smB, H4, 8, lane, acc);
            const float bcv = bc[j];
#pragma unroll
            for (int bb = 0; bb < 8; ++bb) {
                float s = wsum(acc[bb]);
                if (lane == bb) g_co[(s0 + bb) * H + j] = tanhf(s + bcv);
            }
        }
        sbar(nblk, bx, ++gen);

        // ---- P6: mel + gate projections (write only live cells) ----
        for (int c = wg; c <= MEL; c += NWG) {
            float acc[8];
#pragma unroll
            for (int i = 0; i < 8; ++i) acc[i] = 0.f;
            const float4* wp = reinterpret_cast<const float4*>(
                (c < MEL) ? (Wp + (size_t)c * H) : Wg);
            dot1(wp, reinterpret_cast<const float4*>(g_co) + (size_t)s0 * H4,
                 H4, 8, lane, acc);
            const float bias = (c < MEL) ? bp[c] : bg[0];
#pragma unroll
            for (int bb = 0; bb < 8; ++bb) {
                float s = wsum(acc[bb]);
                if (lane == bb) {
                    const int slot = s0 + bb;
                    const int bo   = g_perm[slot];
                    const bool live = step <= lens[bo];
                    if (c < MEL) {
                        const float val = s + bias;
                        g_decin[slot * MEL + c] = val;
                        if (live)
                            __stcs(&out[((size_t)bo * TMEL + step) * MEL + c], val);
                    } else if (live) {
                        __stcs(&out[OFF_GATE + (size_t)bo * TMEL + step], s + bias);
                    }
                }
            }
        }
        sbar(nblk, bx, ++gen);
    }
}

// ---------------- host launch -------------------------------------------------
extern "C" void kernel_launch(void* const* d_in, const int* in_sizes, int n_in,
                              void* d_out, int out_size) {
    (void)in_sizes; (void)n_in; (void)out_size;
    int dev = 0;
    cudaGetDevice(&dev);
    int sms = 0;
    cudaDeviceGetAttribute(&sms, cudaDevAttrMultiProcessorCount, dev);
    if (sms <= 0) sms = 148;
    if (sms > 152) sms = 152;

    const int smem_bytes = 4096 * 16;         // 64 KB dynamic smem
    cudaFuncSetAttribute(decoder_kernel,
                         cudaFuncAttributeMaxDynamicSharedMemorySize, smem_bytes);

    decoder_kernel<<<sms, 512, smem_bytes>>>(
        (const float*)d_in[0],   // encoder_hidden [4,B,H]
        (const float*)d_in[1],   // encoder_outputs [B,TENC,H]
        (const int*)d_in[3],     // mel_spec_lens [B]   (d_in[2] = y, unused)
        (const float*)d_in[4],  (const float*)d_in[5],    // W_attn, b_attn
        (const float*)d_in[6],  (const float*)d_in[7],    // W_ih0, W_hh0
        (const float*)d_in[8],  (const float*)d_in[9],    // b_ih0, b_hh0
        (const float*)d_in[10], (const float*)d_in[11],   // W_ih1, W_hh1
        (const float*)d_in[12], (const float*)d_in[13],   // b_ih1, b_hh1
        (const float*)d_in[14], (const float*)d_in[15],   // Wc, bc
        (const float*)d_in[16], (const float*)d_in[17],   // Wp, bp
        (const float*)d_in[18], (const float*)d_in[19],   // Wg, bg
        (float*)d_out, sms);
}

// round 17
// speedup vs baseline: 1.5025x; 1.1396x over previous
#include <cuda_runtime.h>
#include <cuda_fp16.h>
#include <cstdint>

constexpr int B    = 32;
constexpr int H    = 1024;
constexpr int MEL  = 128;
constexpr int TENC = 512;
constexpr int TMEL = 400;
constexpr int H4   = H / 4;

constexpr size_t OFF_GATE = (size_t)B * TMEL * MEL;
constexpr size_t OFF_MASK = OFF_GATE + (size_t)B * TMEL;

// ---------------- device scratch (no allocations allowed) -------------------
__device__ float g_WT[(size_t)H * H];       // W_attn^T
__device__ __half g_ench[(size_t)B * TENC * H];   // fp16 enc copy (orig batch idx)
__device__ float g_h0[2][B * H];            // slot-indexed
__device__ float g_h1[2][B * H];
__device__ float g_decin[B * MEL];
__device__ float g_v[B * H];
__device__ float g_co[B * H];
__device__ int   g_perm[B];                 // slot -> original batch
// attention partials: 8 t-tiles of 64 (slot-indexed)
__device__ float pm[8][B];
__device__ float pl[8][B];
__device__ float pctx[8][B * H];

// barriers
__device__ unsigned g_bar_arrive = 0;
__device__ volatile unsigned g_bar_gen = 0;
__device__ volatile unsigned g_arr[152 * 8];
__device__ volatile unsigned g_rel[4 * 32];   // one release word per group

// ---------------- helpers ----------------------------------------------------
__device__ __forceinline__ float wsum(float v) {
    v += __shfl_xor_sync(0xffffffffu, v, 16);
    v += __shfl_xor_sync(0xffffffffu, v, 8);
    v += __shfl_xor_sync(0xffffffffu, v, 4);
    v += __shfl_xor_sync(0xffffffffu, v, 2);
    v += __shfl_xor_sync(0xffffffffu, v, 1);
    return v;
}
__device__ __forceinline__ float dot4(float4 a, float4 b, float acc) {
    acc = fmaf(a.x, b.x, acc);
    acc = fmaf(a.y, b.y, acc);
    acc = fmaf(a.z, b.z, acc);
    acc = fmaf(a.w, b.w, acc);
    return acc;
}
__device__ __forceinline__ float sigmoidf_(float x) { return 1.f / (1.f + expf(-x)); }

__device__ __forceinline__ void abar(int nblk) {
    __syncthreads();
    if (threadIdx.x == 0) {
        __threadfence();
        unsigned gen = g_bar_gen;
        if (atomicAdd(&g_bar_arrive, 1u) == (unsigned)nblk - 1u) {
            g_bar_arrive = 0;
            __threadfence();
            g_bar_gen = gen + 1u;
        } else {
            while (g_bar_gen == gen) { __nanosleep(64); }
        }
        __threadfence();
    }
    __syncthreads();
}

// group-local barrier: arrive slots in [b0g, b0g+ng), leader (bxg==0) scans,
// others poll the group's release word.
__device__ __forceinline__ void sbarg(int g, int b0g, int ng, int bxg, unsigned gen) {
    __syncthreads();
    if (threadIdx.x == 0) { __threadfence(); g_arr[(b0g + bxg) * 8] = gen; }
    if (bxg == 0) {
        if (threadIdx.x < 32) {
            for (;;) {
                bool ok = true;
                for (int i = threadIdx.x; i < ng; i += 32)
                    ok &= (g_arr[(b0g + i) * 8] >= gen);
                if (__all_sync(0xffffffffu, ok)) break;
            }
            if (threadIdx.x == 0) { __threadfence(); g_rel[g * 32] = gen; }
        }
    } else if (threadIdx.x == 0) {
        while (g_rel[g * 32] < gen) {}
        __threadfence();
    }
    __syncthreads();
}

__device__ __forceinline__ void stage(float4* dst, const float* src, int n4, int tid) {
    const float4* s = reinterpret_cast<const float4*>(src);
    for (int i = tid; i < n4; i += 512) dst[i] = s[i];
}

// 3-row dot vs 8 batches (acts in smem), weight prefetch depth 2.
__device__ __forceinline__ void dot3(
    const float4* __restrict__ w0, const float4* __restrict__ w1,
    const float4* __restrict__ w2,
    const float4* __restrict__ actb, int bstride4, int nIt, int lane,
    float A0[8], float A1[8], float A2[8])
{
    float4 c0 = w0[lane], c1 = w1[lane], c2 = w2[lane];
    float4 n0 = c0, n1 = c1, n2 = c2;
    if (nIt > 1) { n0 = w0[lane + 32]; n1 = w1[lane + 32]; n2 = w2[lane + 32]; }
    for (int i = 0; i < nIt; ++i) {
        float4 p0 = n0, p1 = n1, p2 = n2;
        if (i + 2 < nIt) {
            p0 = w0[lane + (i + 2) * 32];
            p1 = w1[lane + (i + 2) * 32];
            p2 = w2[lane + (i + 2) * 32];
        }
        const float4* a = actb + i * 32 + lane;
#pragma unroll
        for (int bb = 0; bb < 8; ++bb) {
            float4 av = a[bb * bstride4];
            A0[bb] = dot4(c0, av, A0[bb]);
            A1[bb] = dot4(c1, av, A1[bb]);
            A2[bb] = dot4(c2, av, A2[bb]);
        }
        c0 = n0; c1 = n1; c2 = n2;
        n0 = p0; n1 = p1; n2 = p2;
    }
}

// 1-row dot vs 8 batches, prefetch depth 2.
__device__ __forceinline__ void dot1(
    const float4* __restrict__ w,
    const float4* __restrict__ actb, int bstride4, int nIt, int lane,
    float A[8])
{
    float4 c = w[lane];
    float4 n = c;
    if (nIt > 1) n = w[lane + 32];
    for (int i = 0; i < nIt; ++i) {
        float4 p = n;
        if (i + 2 < nIt) p = w[lane + (i + 2) * 32];
        const float4* a = actb + i * 32 + lane;
#pragma unroll
        for (int bb = 0; bb < 8; ++bb)
            A[bb] = dot4(c, a[bb * bstride4], A[bb]);
        c = n; n = p;
    }
}

// merged GRU cell for one group of 8 slots, acts in smem
__device__ __forceinline__ void gru_sm(
    int j, int lane, int s0,
    const float4* __restrict__ smX, int XD4, int nItX,
    const float4* __restrict__ smH, const float* __restrict__ smHf,
    float* __restrict__ hnew,
    const float* __restrict__ Wih, const float* __restrict__ Whh,
    const float* __restrict__ bih, const float* __restrict__ bhh)
{
    const int XD = XD4 << 2;
    float ar[8], az[8], ani[8], anh[8];
#pragma unroll
    for (int i = 0; i < 8; ++i) { ar[i] = 0.f; az[i] = 0.f; ani[i] = 0.f; anh[i] = 0.f; }

    dot3(reinterpret_cast<const float4*>(Wih + (size_t)j * XD),
         reinterpret_cast<const float4*>(Wih + (size_t)(H + j) * XD),
         reinterpret_cast<const float4*>(Wih + (size_t)(2 * H + j) * XD),
         smX, XD4, nItX, lane, ar, az, ani);
    dot3(reinterpret_cast<const float4*>(Whh + (size_t)j * H),
         reinterpret_cast<const float4*>(Whh + (size_t)(H + j) * H),
         reinterpret_cast<const float4*>(Whh + (size_t)(2 * H + j) * H),
         smH, H4, 8, lane, ar, az, anh);

    const float br  = bih[j] + bhh[j];
    const float bz  = bih[H + j] + bhh[H + j];
    const float bni = bih[2 * H + j];
    const float bnh = bhh[2 * H + j];
#pragma unroll
    for (int bb = 0; bb < 8; ++bb) {
        float r  = wsum(ar[bb]);
        float z  = wsum(az[bb]);
        float ni = wsum(ani[bb]);
        float nh = wsum(anh[bb]);
        if (lane == bb) {
            float rr = sigmoidf_(r + br);
            float zz = sigmoidf_(z + bz);
            float hp = smHf[bb * H + j];
            float nn = tanhf(ni + bni + rr * (nh + bnh));
            hnew[(s0 + bb) * H + j] = (1.f - zz) * nn + zz * hp;
        }
    }
}

// ---------------- main persistent kernel -------------------------------------
__global__ void __launch_bounds__(512, 1)
decoder_kernel(const float* __restrict__ enc_hidden,
               const float* __restrict__ enc_out,
               const int*   __restrict__ lens,
               const float* __restrict__ W_attn, const float* __restrict__ b_attn,
               const float* __restrict__ Wih0, const float* __restrict__ Whh0,
               const float* __restrict__ bih0, const float* __restrict__ bhh0,
               const float* __restrict__ Wih1, const float* __restrict__ Whh1,
               const float* __restrict__ bih1, const float* __restrict__ bhh1,
               const float* __restrict__ Wc,   const float* __restrict__ bc,
               const float* __restrict__ Wp,   const float* __restrict__ bp,
               const float* __restrict__ Wg,   const float* __restrict__ bg,
               float* __restrict__ out, int nblk) {
    extern __shared__ float4 sm4[];
    float4* smA = sm4;                 // 32 KB (2048 f4)
    float4* smB = sm4 + 2048;          // 32 KB
    const float* smBf = reinterpret_cast<const float*>(smB);
    float* smV = reinterpret_cast<float*>(sm4);   // ATT: v[slot] (4 KB)

    __shared__ float smS[16];
    __shared__ float smP[16];
    __shared__ float smW[64];          // 8 tiles x 8 slots

    const int tid  = threadIdx.x;
    const int lane = tid & 31;
    const int wid  = tid >> 5;
    const int bx   = blockIdx.x;
    const int gtid = bx * blockDim.x + tid;
    const int gsz  = nblk * blockDim.x;

    // ---- sort batches by lens (every thread, O(32^2)) ----
    int lensv[B];
#pragma unroll
    for (int b = 0; b < B; ++b) lensv[b] = lens[b];
    int permL[B];
#pragma unroll
    for (int b = 0; b < B; ++b) {
        int r = 0;
#pragma unroll
        for (int b2 = 0; b2 < B; ++b2)
            r += (lensv[b2] < lensv[b]) || (lensv[b2] == lensv[b] && b2 < b);
        permL[r] = b;
    }
    int gm[4];
    gm[0] = lensv[permL[7]];
    gm[1] = lensv[permL[15]];
    gm[2] = lensv[permL[23]];
    gm[3] = lensv[permL[31]];

    // ---- SM partition proportional to group lifetime ----
    const int S = gm[0] + gm[1] + gm[2] + gm[3];
    int n0 = nblk * gm[0] / S; if (n0 < 2) n0 = 2;
    int n1 = nblk * gm[1] / S; if (n1 < 2) n1 = 2;
    int n2 = nblk * gm[2] / S; if (n2 < 2) n2 = 2;
    int n3 = nblk - n0 - n1 - n2;       // largest group absorbs remainder

    int g, b0g, ng;
    if (bx < n0)                { g = 0; b0g = 0;            ng = n0; }
    else if (bx < n0 + n1)      { g = 1; b0g = n0;           ng = n1; }
    else if (bx < n0 + n1 + n2) { g = 2; b0g = n0 + n1;      ng = n2; }
    else                        { g = 3; b0g = n0 + n1 + n2; ng = n3; }
    const int bxg = bx - b0g;
    const int s0  = g * 8;
    const int wg  = bxg * 16 + wid;
    const int NWG = ng * 16;
    const int mg  = (gm[g] < TMEL - 1) ? gm[g] : (TMEL - 1);

    // ================= init =================
    if (gtid < B) g_perm[gtid] = permL[gtid];
    for (int i = gtid; i < H * H; i += gsz) {
        int c = i >> 10, j = i & (H - 1);
        g_WT[i] = W_attn[(size_t)j * H + c];
    }
    for (size_t i = gtid; i < (size_t)B * TENC * H; i += gsz)
        g_ench[i] = __float2half(enc_out[i]);
    for (int i = gtid; i < B * H; i += gsz) {
        int slot = i >> 10, j = i & (H - 1);
        int bo = permL[slot];
        g_h0[0][i] = enc_hidden[bo * H + j];
        g_h1[0][i] = enc_hidden[B * H + bo * H + j];
    }
    for (int i = gtid; i < B * MEL; i += gsz) g_decin[i] = 0.f;
    for (int i = gtid; i < B * TMEL; i += gsz) {
        int b = i / TMEL, t = i - b * TMEL;
        bool msk = t > lensv[b];
        out[OFF_MASK + i] = msk ? 1.f : 0.f;
        if (msk) out[OFF_GATE + i] = 1000.f;
    }
    for (size_t i = gtid; i < (size_t)B * TMEL * MEL; i += gsz) {
        int b = (int)(i / (TMEL * MEL));
        int t = (int)((i / MEL) % TMEL);
        if (t > lensv[b]) out[i] = 0.f;
    }
    for (int i = gtid; i < 152 * 8; i += gsz) g_arr[i] = 0u;
    for (int i = gtid; i < 4 * 32; i += gsz) g_rel[i] = 0u;
    abar(nblk);

    unsigned gen = 0;

    // ================= group-local autoregressive loop ========================
    for (int step = 0; step <= mg; ++step) {
        const int cur = step & 1, nxt = cur ^ 1;

        // ---- GRU layer 0 ----
        stage(smA, g_decin + s0 * MEL, 256, tid);
        stage(smB, g_h0[cur] + s0 * H, 2048, tid);
        __syncthreads();
        for (int j = wg; j < H; j += NWG)
            gru_sm(j, lane, s0, smA, MEL / 4, 1, smB, smBf,
                   g_h0[nxt], Wih0, Whh0, bih0, bhh0);
        sbarg(g, b0g, ng, bxg, ++gen);

        // ---- GRU layer 1 ----
        stage(smA, g_h0[nxt] + s0 * H, 2048, tid);
        stage(smB, g_h1[cur] + s0 * H, 2048, tid);
        __syncthreads();
        for (int j = wg; j < H; j += NWG)
            gru_sm(j, lane, s0, smA, H4, 8, smB, smBf,
                   g_h1[nxt], Wih1, Whh1, bih1, bhh1);
        sbarg(g, b0g, ng, bxg, ++gen);

        // ---- Pv: v = W_attn^T h1 (bias drops in softmax) ----
        stage(smA, g_h1[nxt] + s0 * H, 2048, tid);
        __syncthreads();
        for (int c = wg; c < H; c += NWG) {
            float acc[8];
#pragma unroll
            for (int i = 0; i < 8; ++i) acc[i] = 0.f;
            dot1(reinterpret_cast<const float4*>(g_WT + (size_t)c * H),
                 smA, H4, 8, lane, acc);
#pragma unroll
            for (int bb = 0; bb < 8; ++bb) {
                float s = wsum(acc[bb]);
                if (lane == bb) g_v[(s0 + bb) * H + c] = s;
            }
        }
        sbarg(g, b0g, ng, bxg, ++gen);

        // ---- ATT: fused scores+softmax+context, 8 tiles of 64 t (64 jobs) ----
        for (int job = bxg; job < 64; job += ng) {
            const int slot = s0 + (job >> 3);
            const int bo   = g_perm[slot];
            const int tile = job & 7;
            const int t0   = tile * 64;
            __syncthreads();
            for (int i = tid; i < 1024; i += 512) smV[i] = g_v[slot * H + i];
            __syncthreads();

            float m_run = -1e30f, l_run = 0.f;
            float a0 = 0.f, a1 = 0.f;
            const int hc = wid * 64;

            for (int sub = 0; sub < 4; ++sub) {
                const int ts = t0 + sub * 16;
                {
                    const __half2* er = reinterpret_cast<const __half2*>(
                        g_ench + ((size_t)bo * TENC + ts + wid) * H);
                    const float4* v4 = reinterpret_cast<const float4*>(smV);
                    float acc = 0.f;
#pragma unroll
                    for (int k = 0; k < 8; ++k) {
                        const int idx = k * 32 + lane;
                        float2 f01 = __half22float2(er[2 * idx]);
                        float2 f23 = __half22float2(er[2 * idx + 1]);
                        float4 vv = v4[idx];
                        acc = fmaf(vv.x, f01.x, fmaf(vv.y, f01.y,
                              fmaf(vv.z, f23.x, fmaf(vv.w, f23.y, acc))));
                    }
                    acc = wsum(acc);
                    if (lane == 0) smS[wid] = acc;
                }
                __syncthreads();
                float msub = -1e30f;
#pragma unroll
                for (int i = 0; i < 16; ++i) msub = fmaxf(msub, smS[i]);
                const float m_new = fmaxf(m_run, msub);
                if (lane == 0) smP[wid] = expf(smS[wid] - m_new);
                const float scale = expf(m_run - m_new);
                __syncthreads();
                a0 *= scale; a1 *= scale;
                float lsub = 0.f;
                const __half* eb = g_ench + ((size_t)bo * TENC + ts) * H + hc + lane;
#pragma unroll 4
                for (int t = 0; t < 16; ++t) {
                    float p = smP[t];
                    lsub += p;
                    a0 = fmaf(p, __half2float(eb[(size_t)t * H]), a0);
                    a1 = fmaf(p, __half2float(eb[(size_t)t * H + 32]), a1);
                }
                l_run = l_run * scale + lsub;
                m_run = m_new;
                __syncthreads();
            }
            pctx[tile][slot * H + hc + lane]      = a0;
            pctx[tile][slot * H + hc + 32 + lane] = a1;
            if (tid == 0) { pm[tile][slot] = m_run; pl[tile][slot] = l_run; }
        }
        sbarg(g, b0g, ng, bxg, ++gen);

        const float* h1n = g_h1[nxt];

        // ---- P5: combine 8 ctx tiles + [h1; ctx] GEMM ----
        if (tid < 8) {
            const int slot = s0 + tid;
            float M = -1e30f;
#pragma unroll
            for (int t = 0; t < 8; ++t) M = fmaxf(M, pm[t][slot]);
            float ev[8];
            float L = 0.f;
#pragma unroll
            for (int t = 0; t < 8; ++t) {
                ev[t] = expf(pm[t][slot] - M);
                L += ev[t] * pl[t][slot];
            }
            const float invL = 1.f / L;
#pragma unroll
            for (int t = 0; t < 8; ++t) smW[t * 8 + tid] = ev[t] * invL;
        }
        stage(smA, h1n + s0 * H, 2048, tid);
        __syncthreads();
        for (int i = tid; i < 2048; i += 512) {
            const int bl = i >> 8;
            const size_t off = (size_t)(s0 + bl) * 256 + (i & 255);
            float4 r = make_float4(0.f, 0.f, 0.f, 0.f);
#pragma unroll
            for (int t = 0; t < 8; ++t) {
                const float w = smW[t * 8 + bl];
                float4 c = reinterpret_cast<const float4*>(pctx[t])[off];
                r.x = fmaf(w, c.x, r.x);
                r.y = fmaf(w, c.y, r.y);
                r.z = fmaf(w, c.z, r.z);
                r.w = fmaf(w, c.w, r.w);
            }
            smB[i] = r;
        }
        __syncthreads();
        for (int j = wg; j < H; j += NWG) {
            float acc[8];
#pragma unroll
            for (int i = 0; i < 8; ++i) acc[i] = 0.f;
            dot1(reinterpret_cast<const float4*>(Wc + (size_t)j * 2 * H),
                 smA, H4, 8, lane, acc);
            dot1(reinterpret_cast<const float4*>(Wc + (size_t)j * 2 * H) + H4,
                 smB, H4, 8, lane, acc);
            const float bcv = bc[j];
#pragma unroll
            for (int bb = 0; bb < 8; ++bb) {
                float s = wsum(acc[bb]);
                if (lane == bb) g_co[(s0 + bb) * H + j] = tanhf(s + bcv);
            }
        }
        sbarg(g, b0g, ng, bxg, ++gen);

        // ---- P6: mel + gate projections (write only live cells) ----
        for (int c = wg; c <= MEL; c += NWG) {
            float acc[8];
#pragma unroll
            for (int i = 0; i < 8; ++i) acc[i] = 0.f;
            const float4* wp = reinterpret_cast<const float4*>(
                (c < MEL) ? (Wp + (size_t)c * H) : Wg);
            dot1(wp, reinterpret_cast<const float4*>(g_co) + (size_t)s0 * H4,
                 H4, 8, lane, acc);
            const float bias = (c < MEL) ? bp[c] : bg[0];
#pragma unroll
            for (int bb = 0; bb < 8; ++bb) {
                float s = wsum(acc[bb]);
                if (lane == bb) {
                    const int slot = s0 + bb;
                    const int bo   = g_perm[slot];
                    const bool live = step <= lensv[bo];
                    if (c < MEL) {
                        const float val = s + bias;
                        g_decin[slot * MEL + c] = val;
                        if (live)
                            __stcs(&out[((size_t)bo * TMEL + step) * MEL + c], val);
                    } else if (live) {
                        __stcs(&out[OFF_GATE + (size_t)bo * TMEL + step], s + bias);
                    }
                }
            }
        }
        sbarg(g, b0g, ng, bxg, ++gen);
    }
}

// ---------------- host launch -------------------------------------------------
extern "C" void kernel_launch(void* const* d_in, const int* in_sizes, int n_in,
                              void* d_out, int out_size) {
    (void)in_sizes; (void)n_in; (void)out_size;
    int dev = 0;
    cudaGetDevice(&dev);
    int sms = 0;
    cudaDeviceGetAttribute(&sms, cudaDevAttrMultiProcessorCount, dev);
    if (sms <= 0) sms = 148;
    if (sms > 152) sms = 152;

    const int smem_bytes = 4096 * 16;         // 64 KB dynamic smem
    cudaFuncSetAttribute(decoder_kernel,
                         cudaFuncAttributeMaxDynamicSharedMemorySize, smem_bytes);

    decoder_kernel<<<sms, 512, smem_bytes>>>(
        (const float*)d_in[0],   // encoder_hidden [4,B,H]
        (const float*)d_in[1],   // encoder_outputs [B,TENC,H]
        (const int*)d_in[3],     // mel_spec_lens [B]   (d_in[2] = y, unused)
        (const float*)d_in[4],  (const float*)d_in[5],    // W_attn, b_attn
        (const float*)d_in[6],  (const float*)d_in[7],    // W_ih0, W_hh0
        (const float*)d_in[8],  (const float*)d_in[9],    // b_ih0, b_hh0
        (const float*)d_in[10], (const float*)d_in[11],   // W_ih1, W_hh1
        (const float*)d_in[12], (const float*)d_in[13],   // b_ih1, b_hh1
        (const float*)d_in[14], (const float*)d_in[15],   // Wc, bc
        (const float*)d_in[16], (const float*)d_in[17],   // Wp, bp
        (const float*)d_in[18], (const float*)d_in[19],   // Wg, bg
        (float*)d_out, sms);
}